// round 8
// baseline (speedup 1.0000x reference)
#include <cuda_runtime.h>
#include <cstdint>
#include <cstddef>

// Problem constants
#define LP   197
#define BT   128
#define DIM  768
#define CA   192
#define TT   8
#define ROWS 64          // rows per CTA (two CTAs per position l)

// SMEM layout (floats)
#define GP    196              // Gs: 64 x 196 (h/gelu tile); odd granules -> LDSM-clean
#define GS_F  (ROWS * GP)      // 12544
#define AP    36               // GEMM1 A stage: 64 x 36 (k-chunk 32)
#define B1P   200              // GEMM1 w1 stage: 32 x 200
#define AS_F  (ROWS * AP)      // 2304
#define BP2   52               // GEMM2 w2t stage pitch ([n][k], 13 granules, odd)
#define KST2  48               // GEMM2 k-stage size
#define WS2_F (128 * BP2)      // 6656 per buffer, x2 buffers

#define SMEM_FLOATS (GS_F + 2 * WS2_F)   // 25856
#define SMEM_BYTES  (SMEM_FLOATS * 4)    // 103424 -> 2 CTAs/SM

// Pre-transposed w2 (n-major, k contiguous): [n=768][k=192]
__device__ float g_w2t[DIM * CA];

__device__ __forceinline__ void ldsm_x4(uint32_t a[4], uint32_t saddr) {
    asm volatile("ldmatrix.sync.aligned.m8n8.x4.shared.b16 {%0,%1,%2,%3}, [%4];\n"
                 : "=r"(a[0]), "=r"(a[1]), "=r"(a[2]), "=r"(a[3]) : "r"(saddr));
}

__device__ __forceinline__ void mma_tf32(float c[4], const uint32_t a[4], const uint32_t b[2]) {
    asm volatile(
        "mma.sync.aligned.m16n8k8.row.col.f32.tf32.tf32.f32 "
        "{%0,%1,%2,%3}, {%4,%5,%6,%7}, {%8,%9}, {%0,%1,%2,%3};\n"
        : "+f"(c[0]), "+f"(c[1]), "+f"(c[2]), "+f"(c[3])
        : "r"(a[0]), "r"(a[1]), "r"(a[2]), "r"(a[3]),
          "r"(b[0]), "r"(b[1]));
}

__device__ __forceinline__ float gelu_exact(float v) {
    return 0.5f * v * (1.0f + erff(v * 0.70710678118654752f));
}

// w2t[n][k] = w2[k][n];  w2 is [192][768]
__global__ void transpose_w2_kernel(const float* __restrict__ w2,
                                    float* __restrict__ w2t) {
    __shared__ float t[32][33];
    int bx = blockIdx.x * 32, by = blockIdx.y * 32;   // bx over n(768), by over k(192)
    int tx = threadIdx.x, ty = threadIdx.y;           // 32 x 8
    #pragma unroll
    for (int i = 0; i < 32; i += 8)
        t[ty + i][tx] = w2[(size_t)(by + ty + i) * DIM + bx + tx];
    __syncthreads();
    #pragma unroll
    for (int i = 0; i < 32; i += 8)
        w2t[(size_t)(bx + ty + i) * CA + by + tx] = t[tx][ty + i];
}

__global__ void __launch_bounds__(256, 2)
fused_adapter_kernel(const float* __restrict__ x,
                     const float* __restrict__ w1,
                     const float* __restrict__ b1,
                     const float* __restrict__ cw,   // (CA,3)
                     const float* __restrict__ cb,   // (CA,)
                     const float* __restrict__ b2,
                     float* __restrict__ out)
{
    extern __shared__ float smem[];
    float* Gs = smem;                 // 64 x GP
    float* Wt = smem + GS_F;          // GEMM2 w2t double-buffer; GEMM1 stage aliases here
    float* As = Wt;                   // GEMM1 A stage (64 x AP)
    float* Bs = Wt + AS_F;            // GEMM1 w1 stage (32 x B1P)

    const uint32_t smem_u = (uint32_t)__cvta_generic_to_shared(smem);
    const uint32_t Wt_u   = smem_u + GS_F * 4;

    const int tid  = threadIdx.x;
    const int wid  = tid >> 5;
    const int lane = tid & 31;
    const int gid  = lane >> 2;   // 0..7
    const int ctig = lane & 3;    // 0..3

    const int l    = blockIdx.x >> 1;
    const int half = blockIdx.x & 1;
    const int lsrc = (l == 0) ? 1 : l;

    const int wm  = wid & 1;
    const int wn1 = wid >> 1;

    // ldmatrix per-lane offsets (words)
    const int a_lane_off = (lane & 15) * AP + ((lane >> 4) << 2);
    const int g_lane_off = (lane & 15) * GP + ((lane >> 4) << 2);
    // B fragment (n-major, k-contig): tiles (n+0,k+0),(n+0,k+4),(n+8,k+0),(n+8,k+4)
    const int bn_add = (lane & 7) + ((lane >> 4) << 3);
    const int bk_add = ((lane >> 3) & 1) << 2;
    const int b2_lane_off = bn_add * BP2 + bk_add;

    const float* xA = x + ((size_t)lsrc * BT + half * ROWS) * DIM;

    // ================= GEMM1 (R4-proven): reg-prefetch double buffering =========
    float acc[2][6][4];
    #pragma unroll
    for (int i = 0; i < 2; i++)
        #pragma unroll
        for (int j = 0; j < 6; j++)
            #pragma unroll
            for (int k = 0; k < 4; k++) acc[i][j][k] = 0.0f;

    float4 xreg[2];
    float4 w1reg[6];

    // prefetch chunk 0
    #pragma unroll
    for (int i = 0; i < 2; i++) {
        int idx = tid + (i << 8);
        int row = idx >> 3;
        int c4  = (idx & 7) << 2;
        xreg[i] = *(const float4*)(xA + (size_t)row * DIM + c4);
    }
    #pragma unroll
    for (int i = 0; i < 6; i++) {
        int idx = tid + (i << 8);
        int row = idx / 48;
        int c4  = (idx % 48) << 2;
        w1reg[i] = *(const float4*)(w1 + (size_t)row * CA + c4);
    }

    #pragma unroll 1
    for (int kc = 0; kc < DIM; kc += 32) {
        // commit prefetched chunk to smem
        #pragma unroll
        for (int i = 0; i < 2; i++) {
            int idx = tid + (i << 8);
            int row = idx >> 3;
            int c4  = (idx & 7) << 2;
            *(float4*)(As + row * AP + c4) = xreg[i];
        }
        #pragma unroll
        for (int i = 0; i < 6; i++) {
            int idx = tid + (i << 8);
            int row = idx / 48;
            int c4  = (idx % 48) << 2;
            *(float4*)(Bs + row * B1P + c4) = w1reg[i];
        }
        __syncthreads();

        // prefetch next chunk (overlaps MMA)
        if (kc + 32 < DIM) {
            #pragma unroll
            for (int i = 0; i < 2; i++) {
                int idx = tid + (i << 8);
                int row = idx >> 3;
                int c4  = (idx & 7) << 2;
                xreg[i] = *(const float4*)(xA + (size_t)row * DIM + kc + 32 + c4);
            }
            #pragma unroll
            for (int i = 0; i < 6; i++) {
                int idx = tid + (i << 8);
                int row = idx / 48;
                int c4  = (idx % 48) << 2;
                w1reg[i] = *(const float4*)(w1 + (size_t)(kc + 32 + row) * CA + c4);
            }
        }

        #pragma unroll
        for (int ks = 0; ks < 4; ks++) {
            int k0 = ks << 3;
            uint32_t a0[4], a1[4];
            ldsm_x4(a0, Wt_u + ((wm * 32 +  0) * AP + k0 + a_lane_off) * 4);
            ldsm_x4(a1, Wt_u + ((wm * 32 + 16) * AP + k0 + a_lane_off) * 4);
            #pragma unroll
            for (int nt = 0; nt < 6; nt++) {
                uint32_t b[2];
                int n0 = wn1 * 48 + nt * 8 + gid;
                b[0] = __float_as_uint(Bs[(k0 + ctig) * B1P + n0]);
                b[1] = __float_as_uint(Bs[(k0 + ctig + 4) * B1P + n0]);
                mma_tf32(acc[0][nt], a0, b);
                mma_tf32(acc[1][nt], a1, b);
            }
        }
        __syncthreads();
    }

    // store h + b1 into Gs
    #pragma unroll
    for (int mt = 0; mt < 2; mt++) {
        #pragma unroll
        for (int nt = 0; nt < 6; nt++) {
            int r0 = wm * 32 + mt * 16 + gid;
            int c0 = wn1 * 48 + nt * 8 + 2 * ctig;
            float bb0 = b1[c0], bb1 = b1[c0 + 1];
            Gs[r0 * GP + c0]           = acc[mt][nt][0] + bb0;
            Gs[r0 * GP + c0 + 1]       = acc[mt][nt][1] + bb1;
            Gs[(r0 + 8) * GP + c0]     = acc[mt][nt][2] + bb0;
            Gs[(r0 + 8) * GP + c0 + 1] = acc[mt][nt][3] + bb1;
        }
    }

    // prefetch GEMM2 stage 0 (nc=0, kst=0: n 0..127, k 0..47), hidden behind GELU
    float4 w2reg[6];
    #pragma unroll
    for (int i = 0; i < 6; i++) {
        int idx = tid + (i << 8);
        int row = idx / 12;
        int c4  = (idx % 12) << 2;
        w2reg[i] = *(const float4*)(g_w2t + (size_t)row * CA + c4);
    }

    __syncthreads();

    // ============ Temporal mixing fused with GELU (l >= 1), else GELU only ======
    if (l > 0) {
        #pragma unroll 1
        for (int i = 0; i < 6; i++) {
            int task = tid + (i << 8);
            int b = task / CA;
            int c = task % CA;
            float cw0 = cw[c * 3 + 0];
            float cw1 = cw[c * 3 + 1];
            float cw2 = cw[c * 3 + 2];
            float cbc = cb[c];
            float hv[TT];
            float S = 0.0f;
            #pragma unroll
            for (int t = 0; t < TT; t++) {
                hv[t] = Gs[(b * TT + t) * GP + c];
                float w = cw1 * (float)t - (float)(TT - 1 - t);
                if (t < TT - 1) w += cw0 * (float)(t + 1);
                if (t >= 1)     w += cw2 * (float)(t - 1);
                S += w * hv[t];
            }
            float r = S * (1.0f / 28.0f) + cbc;
            #pragma unroll
            for (int t = 0; t < TT; t++)
                Gs[(b * TT + t) * GP + c] = gelu_exact(hv[t] + r);
        }
    } else {
        #pragma unroll 4
        for (int i = 0; i < 48; i++) {
            int idx = tid + (i << 8);
            int r = idx / CA;
            int c = idx % CA;
            Gs[r * GP + c] = gelu_exact(Gs[r * GP + c]);
        }
    }
    __syncthreads();

    // ===== GEMM2: 6 n-chunks of 128, warp tile 32x32 (8 acc chains), LDSM B =====
    const float* xR   = x   + ((size_t)l * BT + half * ROWS) * DIM;
    float*       outR = out + ((size_t)l * BT + half * ROWS) * DIM;

    const int wn2 = wid >> 1;   // 0..3 (32 cols each)
    const int st_row = tid / 12 >= 0 ? 0 : 0;  // (placeholder removed below)

    #pragma unroll 1
    for (int nc = 0; nc < 6; nc++) {
        const int nbase = nc * 128;

        float acc2[2][4][4];
        #pragma unroll
        for (int i = 0; i < 2; i++)
            #pragma unroll
            for (int j = 0; j < 4; j++)
                #pragma unroll
                for (int k = 0; k < 4; k++) acc2[i][j][k] = 0.0f;

        #pragma unroll 1
        for (int kst = 0; kst < 4; kst++) {
            const int s   = nc * 4 + kst;
            const int buf = (s & 1) * WS2_F;

            // STS stage s from regs (float4; BP2=52 keeps 16B alignment)
            #pragma unroll
            for (int i = 0; i < 6; i++) {
                int idx = tid + (i << 8);
                int row = idx / 12;
                int c4  = (idx % 12) << 2;
                *(float4*)(Wt + buf + row * BP2 + c4) = w2reg[i];
            }
            __syncthreads();   // one barrier per stage (write targets other buffer)

            // LDG prefetch stage s+1 into regs (overlaps MMA)
            if (s + 1 < 24) {
                int nc2  = (s + 1) >> 2;
                int kst2 = (s + 1) & 3;
                #pragma unroll
                for (int i = 0; i < 6; i++) {
                    int idx = tid + (i << 8);
                    int row = idx / 12;
                    int c4  = (idx % 12) << 2;
                    w2reg[i] = *(const float4*)(g_w2t +
                        (size_t)(nc2 * 128 + row) * CA + kst2 * KST2 + c4);
                }
            }

            #pragma unroll
            for (int ks = 0; ks < 6; ks++) {
                int k0  = ks << 3;
                int k0g = kst * KST2 + k0;
                uint32_t a0[4], a1[4], bf0[4], bf1[4];
                ldsm_x4(a0, smem_u + ((wm * 32 +  0) * GP + k0g + g_lane_off) * 4);
                ldsm_x4(a1, smem_u + ((wm * 32 + 16) * GP + k0g + g_lane_off) * 4);
                ldsm_x4(bf0, Wt_u + (buf + (wn2 * 32 +  0) * BP2 + k0 + b2_lane_off) * 4);
                ldsm_x4(bf1, Wt_u + (buf + (wn2 * 32 + 16) * BP2 + k0 + b2_lane_off) * 4);
                mma_tf32(acc2[0][0], a0, bf0);
                mma_tf32(acc2[1][0], a1, bf0);
                mma_tf32(acc2[0][1], a0, bf0 + 2);
                mma_tf32(acc2[1][1], a1, bf0 + 2);
                mma_tf32(acc2[0][2], a0, bf1);
                mma_tf32(acc2[1][2], a1, bf1);
                mma_tf32(acc2[0][3], a0, bf1 + 2);
                mma_tf32(acc2[1][3], a1, bf1 + 2);
            }
        }

        // epilogue: + b2 + x residual, store
        #pragma unroll
        for (int mt = 0; mt < 2; mt++) {
            #pragma unroll
            for (int nt = 0; nt < 4; nt++) {
                int r0  = wm * 32 + mt * 16 + gid;
                int c0g = nbase + wn2 * 32 + nt * 8 + 2 * ctig;
                float2 bb = *(const float2*)(b2 + c0g);
                size_t o0 = (size_t)r0 * DIM + c0g;
                float2 xr0 = *(const float2*)(xR + o0);
                float2 ov0;
                ov0.x = xr0.x + acc2[mt][nt][0] + bb.x;
                ov0.y = xr0.y + acc2[mt][nt][1] + bb.y;
                *(float2*)(outR + o0) = ov0;
                size_t o1 = o0 + (size_t)8 * DIM;
                float2 xr1 = *(const float2*)(xR + o1);
                float2 ov1;
                ov1.x = xr1.x + acc2[mt][nt][2] + bb.x;
                ov1.y = xr1.y + acc2[mt][nt][3] + bb.y;
                *(float2*)(outR + o1) = ov1;
            }
        }
    }
}

extern "C" void kernel_launch(void* const* d_in, const int* in_sizes, int n_in,
                              void* d_out, int out_size) {
    const float* x  = (const float*)d_in[0];
    const float* w1 = (const float*)d_in[1];
    const float* b1 = (const float*)d_in[2];
    const float* cw = (const float*)d_in[3];
    const float* cb = (const float*)d_in[4];
    const float* w2 = (const float*)d_in[5];
    const float* b2 = (const float*)d_in[6];
    float* out = (float*)d_out;

    float* w2t;
    cudaGetSymbolAddress((void**)&w2t, g_w2t);
    transpose_w2_kernel<<<dim3(DIM / 32, CA / 32), dim3(32, 8)>>>(w2, w2t);

    cudaFuncSetAttribute(fused_adapter_kernel,
                         cudaFuncAttributeMaxDynamicSharedMemorySize, SMEM_BYTES);
    fused_adapter_kernel<<<LP * 2, 256, SMEM_BYTES>>>(x, w1, b1, cw, cb, b2, out);
}

// round 10
// speedup vs baseline: 1.2213x; 1.2213x over previous
#include <cuda_runtime.h>
#include <cstdint>
#include <cstddef>

#define LP   197
#define BT   128
#define DIM  768
#define CA   192

// Scratch (device globals; no runtime allocation)
__device__ float g_w1t[CA * DIM];      // w1 transposed: [n=192][k=768]
__device__ float g_w2t[DIM * CA];      // w2 transposed: [n=768][k=192]
__device__ float g_act[LP * BT * CA];  // g = gelu(mix(h)): [25216][192]

// ---------------- PTX helpers ----------------
__device__ __forceinline__ void cp16(uint32_t s, const void* g) {
    asm volatile("cp.async.cg.shared.global [%0], [%1], 16;\n" :: "r"(s), "l"(g));
}
__device__ __forceinline__ void cp_commit() { asm volatile("cp.async.commit_group;\n"); }
__device__ __forceinline__ void cp_wait0()  { asm volatile("cp.async.wait_group 0;\n" ::: "memory"); }

__device__ __forceinline__ void ldsm_x4(uint32_t a[4], uint32_t saddr) {
    asm volatile("ldmatrix.sync.aligned.m8n8.x4.shared.b16 {%0,%1,%2,%3}, [%4];\n"
                 : "=r"(a[0]), "=r"(a[1]), "=r"(a[2]), "=r"(a[3]) : "r"(saddr));
}
__device__ __forceinline__ void mma_tf32(float c[4], const uint32_t a[4], const uint32_t b[2]) {
    asm volatile(
        "mma.sync.aligned.m16n8k8.row.col.f32.tf32.tf32.f32 "
        "{%0,%1,%2,%3}, {%4,%5,%6,%7}, {%8,%9}, {%0,%1,%2,%3};\n"
        : "+f"(c[0]), "+f"(c[1]), "+f"(c[2]), "+f"(c[3])
        : "r"(a[0]), "r"(a[1]), "r"(a[2]), "r"(a[3]), "r"(b[0]), "r"(b[1]));
}
__device__ __forceinline__ float gelu_exact(float v) {
    return 0.5f * v * (1.0f + erff(v * 0.70710678118654752f));
}
__device__ __forceinline__ float red8(float v) {   // sum over gid (lanes ^4,^8,^16)
    v += __shfl_xor_sync(0xffffffffu, v, 4);
    v += __shfl_xor_sync(0xffffffffu, v, 8);
    v += __shfl_xor_sync(0xffffffffu, v, 16);
    return v;
}

// ----- prep: w1t[n][k]=w1[k][n]; w2t[n][k]=w2[k][n] -----
__global__ void transpose_both_kernel(const float* __restrict__ w1,
                                      const float* __restrict__ w2,
                                      float* __restrict__ w1t,
                                      float* __restrict__ w2t) {
    __shared__ float t[32][33];
    int b = blockIdx.x;
    const float* in; float* outp; int R, C, bx, by;
    if (b < 144) { in = w1; outp = w1t; R = DIM; C = CA;  bx = (b % 6) * 32;  by = (b / 6) * 32; }
    else { b -= 144; in = w2; outp = w2t; R = CA;  C = DIM; bx = (b % 24) * 32; by = (b / 24) * 32; }
    int tx = threadIdx.x, ty = threadIdx.y;
    #pragma unroll
    for (int i = 0; i < 32; i += 8)
        t[ty + i][tx] = in[(size_t)(by + ty + i) * C + bx + tx];
    __syncthreads();
    #pragma unroll
    for (int i = 0; i < 32; i += 8)
        outp[(size_t)(bx + ty + i) * R + by + tx] = t[tx][ty + i];
}

// ================= G1: g = gelu(mix(x @ w1 + b1)) =================
// CTA: 64 rows x 192 cols, K=768 in 24 chunks of 32, cp.async ping-pong.
#define G1_AP   36
#define G1_AF   (64 * G1_AP)            // 2304
#define G1_BP   36
#define G1_BF   (CA * G1_BP)            // 6912
#define G1_STG  (G1_AF + G1_BF)         // 9216 floats / buffer
#define G1_SMEM (2 * G1_STG * 4)        // 73728 B -> 3 CTAs/SM

__global__ void __launch_bounds__(256, 3)
g1_kernel(const float* __restrict__ x,
          const float* __restrict__ b1,
          const float* __restrict__ cw,
          const float* __restrict__ cb)
{
    extern __shared__ float smem[];
    const uint32_t smem_u = (uint32_t)__cvta_generic_to_shared(smem);

    const int tid  = threadIdx.x;
    const int wid  = tid >> 5;
    const int lane = tid & 31;
    const int gid  = lane >> 2;
    const int ctig = lane & 3;

    const int l    = blockIdx.x >> 1;
    const int half = blockIdx.x & 1;
    const int lsrc = (l == 0) ? 1 : l;
    const float* xA = x + ((size_t)lsrc * BT + half * 64) * DIM;

    const int wm = wid & 1;            // rows wm*32..+31
    const int wn = wid >> 1;           // cols wn*48..+47

    const int a_lane_off = (lane & 15) * G1_AP + ((lane >> 4) << 2);
    const int b_lane_off = ((lane & 7) + ((lane >> 4) << 3)) * G1_BP + (((lane >> 3) & 1) << 2);

    float acc[2][6][4];
    #pragma unroll
    for (int i = 0; i < 2; i++)
        #pragma unroll
        for (int j = 0; j < 6; j++)
            #pragma unroll
            for (int k = 0; k < 4; k++) acc[i][j][k] = 0.0f;

    // stage chunk kc into buffer buf
    auto stage = [&](int buf, int kc) {
        uint32_t base = smem_u + (uint32_t)(buf * G1_STG) * 4;
        #pragma unroll
        for (int i = 0; i < 2; i++) {                 // A: 64x32
            int idx = tid + (i << 8);
            int row = idx >> 3, c4 = (idx & 7) << 2;
            cp16(base + (uint32_t)(row * G1_AP + c4) * 4,
                 xA + (size_t)row * DIM + kc + c4);
        }
        #pragma unroll
        for (int i = 0; i < 6; i++) {                 // B: 192x32 (w1t, k-contig)
            int idx = tid + (i << 8);
            int row = idx >> 3, c4 = (idx & 7) << 2;
            cp16(base + (uint32_t)(G1_AF + row * G1_BP + c4) * 4,
                 g_w1t + (size_t)row * DIM + kc + c4);
        }
        cp_commit();
    };

    stage(0, 0);

    #pragma unroll 1
    for (int ic = 0; ic < 24; ic++) {
        cp_wait0();
        __syncthreads();
        if (ic < 23) stage((ic + 1) & 1, (ic + 1) * 32);

        const uint32_t cu = smem_u + (uint32_t)((ic & 1) * G1_STG) * 4;
        #pragma unroll
        for (int ks = 0; ks < 4; ks++) {
            int k0 = ks << 3;
            uint32_t a0[4], a1[4];
            ldsm_x4(a0, cu + (uint32_t)((wm * 32 +  0) * G1_AP + k0 + a_lane_off) * 4);
            ldsm_x4(a1, cu + (uint32_t)((wm * 32 + 16) * G1_AP + k0 + a_lane_off) * 4);
            #pragma unroll
            for (int p = 0; p < 3; p++) {
                uint32_t bf[4];
                ldsm_x4(bf, cu + (uint32_t)(G1_AF + (wn * 48 + p * 16) * G1_BP + k0 + b_lane_off) * 4);
                mma_tf32(acc[0][2 * p],     a0, bf);
                mma_tf32(acc[1][2 * p],     a1, bf);
                mma_tf32(acc[0][2 * p + 1], a0, bf + 2);
                mma_tf32(acc[1][2 * p + 1], a1, bf + 2);
            }
        }
    }

    // ---- epilogue: +b1, temporal mixing (shfl over gid = frame t), GELU, store g ----
    const float tA0 = (gid < 7) ? (float)(gid + 1) : 0.0f;   // coeff of cw0
    const float tA1 = (float)gid;                            // coeff of cw1
    const float tA2 = (gid >= 1) ? (float)(gid - 1) : 0.0f;  // coeff of cw2
    const float tT7 = (float)(7 - gid);
    const int mbase = (int)((size_t)l * BT) + half * 64;

    #pragma unroll
    for (int nt = 0; nt < 6; nt++) {
        int c = wn * 48 + nt * 8 + 2 * ctig;
        float b1a = b1[c],     b1b = b1[c + 1];
        float cba = cb[c],     cbb = cb[c + 1];
        float aA  = tA0 * cw[3 * c]     + tA1 * cw[3 * c + 1] + tA2 * cw[3 * c + 2] - tT7;
        float aB  = tA0 * cw[3 * c + 3] + tA1 * cw[3 * c + 4] + tA2 * cw[3 * c + 5] - tT7;
        #pragma unroll
        for (int mt = 0; mt < 2; mt++) {
            int r0 = wm * 32 + mt * 16 + gid;
            float v0 = acc[mt][nt][0] + b1a;
            float v1 = acc[mt][nt][1] + b1b;
            float v2 = acc[mt][nt][2] + b1a;   // row r0+8
            float v3 = acc[mt][nt][3] + b1b;
            if (l > 0) {
                float s0 = red8(aA * v0);
                float s1 = red8(aB * v1);
                float s2 = red8(aA * v2);
                float s3 = red8(aB * v3);
                v0 += s0 * (1.0f / 28.0f) + cba;
                v1 += s1 * (1.0f / 28.0f) + cbb;
                v2 += s2 * (1.0f / 28.0f) + cba;
                v3 += s3 * (1.0f / 28.0f) + cbb;
            }
            float* gp0 = g_act + (size_t)(mbase + r0) * CA + c;
            float* gp1 = g_act + (size_t)(mbase + r0 + 8) * CA + c;
            *(float2*)gp0 = make_float2(gelu_exact(v0), gelu_exact(v1));
            *(float2*)gp1 = make_float2(gelu_exact(v2), gelu_exact(v3));
        }
    }
}

// ================= G2: out = g @ w2 + b2 + x =================
// CTA 128(m) x 128(n), K=192 staged in 2 chunks of 96. Grid (197, 6).
#define G2_P    100
#define G2_AF   (128 * G2_P)            // 12800 floats
#define G2_SMEM (2 * G2_AF * 4)         // 102400 B -> 2 CTAs/SM

__global__ void __launch_bounds__(256, 2)
g2_kernel(const float* __restrict__ x,
          const float* __restrict__ b2,
          float* __restrict__ out)
{
    extern __shared__ float smem[];
    const uint32_t As_u = (uint32_t)__cvta_generic_to_shared(smem);
    const uint32_t Bs_u = As_u + (uint32_t)G2_AF * 4;

    const int tid  = threadIdx.x;
    const int wid  = tid >> 5;
    const int lane = tid & 31;
    const int gid  = lane >> 2;
    const int ctig = lane & 3;

    const int mtile = blockIdx.x;      // 0..196
    const int ntile = blockIdx.y;      // 0..5

    const int wm = wid & 1;            // rows wm*64..+63
    const int wn = wid >> 1;           // cols wn*32..+31

    const int a_lane_off = (lane & 15) * G2_P + ((lane >> 4) << 2);
    const int b_lane_off = ((lane & 7) + ((lane >> 4) << 3)) * G2_P + (((lane >> 3) & 1) << 2);

    float acc[4][4][4];
    #pragma unroll
    for (int i = 0; i < 4; i++)
        #pragma unroll
        for (int j = 0; j < 4; j++)
            #pragma unroll
            for (int k = 0; k < 4; k++) acc[i][j][k] = 0.0f;

    const float* Ag = g_act + (size_t)(mtile * BT) * CA;
    const float* Bg = g_w2t + (size_t)(ntile * 128) * CA;

    #pragma unroll 1
    for (int ch = 0; ch < 2; ch++) {
        const int kc = ch * 96;
        // stage A (128x96) and B (128x96)
        #pragma unroll
        for (int i = 0; i < 12; i++) {
            int idx = tid + (i << 8);
            int row = idx / 24, c4 = (idx % 24) << 2;
            cp16(As_u + (uint32_t)(row * G2_P + c4) * 4, Ag + (size_t)row * CA + kc + c4);
            cp16(Bs_u + (uint32_t)(row * G2_P + c4) * 4, Bg + (size_t)row * CA + kc + c4);
        }
        cp_commit();
        cp_wait0();
        __syncthreads();

        #pragma unroll
        for (int ks = 0; ks < 12; ks++) {
            int k0 = ks << 3;
            uint32_t a[4][4];
            #pragma unroll
            for (int mt = 0; mt < 4; mt++)
                ldsm_x4(a[mt], As_u + (uint32_t)((wm * 64 + mt * 16) * G2_P + k0 + a_lane_off) * 4);
            #pragma unroll
            for (int p = 0; p < 2; p++) {
                uint32_t bf[4];
                ldsm_x4(bf, Bs_u + (uint32_t)((wn * 32 + p * 16) * G2_P + k0 + b_lane_off) * 4);
                #pragma unroll
                for (int mt = 0; mt < 4; mt++) {
                    mma_tf32(acc[mt][2 * p],     a[mt], bf);
                    mma_tf32(acc[mt][2 * p + 1], a[mt], bf + 2);
                }
            }
        }
        __syncthreads();   // all warps done before restaging
    }

    // ---- epilogue: +b2 +x residual ----
    const size_t mg0 = (size_t)mtile * BT;
    #pragma unroll
    for (int nt = 0; nt < 4; nt++) {
        int cg = ntile * 128 + wn * 32 + nt * 8 + 2 * ctig;
        float2 bb = *(const float2*)(b2 + cg);
        #pragma unroll
        for (int mt = 0; mt < 4; mt++) {
            int r = wm * 64 + mt * 16 + gid;
            size_t o0 = (mg0 + r) * DIM + cg;
            size_t o1 = o0 + (size_t)8 * DIM;
            float2 x0 = *(const float2*)(x + o0);
            float2 x1 = *(const float2*)(x + o1);
            float2 v0, v1;
            v0.x = acc[mt][nt][0] + bb.x + x0.x;
            v0.y = acc[mt][nt][1] + bb.y + x0.y;
            v1.x = acc[mt][nt][2] + bb.x + x1.x;
            v1.y = acc[mt][nt][3] + bb.y + x1.y;
            *(float2*)(out + o0) = v0;
            *(float2*)(out + o1) = v1;
        }
    }
}

extern "C" void kernel_launch(void* const* d_in, const int* in_sizes, int n_in,
                              void* d_out, int out_size) {
    const float* x  = (const float*)d_in[0];
    const float* w1 = (const float*)d_in[1];
    const float* b1 = (const float*)d_in[2];
    const float* cw = (const float*)d_in[3];
    const float* cb = (const float*)d_in[4];
    const float* w2 = (const float*)d_in[5];
    const float* b2 = (const float*)d_in[6];
    float* out = (float*)d_out;

    float *w1t, *w2t;
    cudaGetSymbolAddress((void**)&w1t, g_w1t);
    cudaGetSymbolAddress((void**)&w2t, g_w2t);

    transpose_both_kernel<<<288, dim3(32, 8)>>>(w1, w2, w1t, w2t);

    cudaFuncSetAttribute(g1_kernel, cudaFuncAttributeMaxDynamicSharedMemorySize, G1_SMEM);
    g1_kernel<<<LP * 2, 256, G1_SMEM>>>(x, b1, cw, cb);

    cudaFuncSetAttribute(g2_kernel, cudaFuncAttributeMaxDynamicSharedMemorySize, G2_SMEM);
    g2_kernel<<<dim3(LP, 6), 256, G2_SMEM>>>(x, b2, out);
}

// round 11
// speedup vs baseline: 1.5177x; 1.2427x over previous
#include <cuda_runtime.h>
#include <cuda_fp16.h>
#include <cstdint>
#include <cstddef>

#define LP   197
#define BT   128
#define DIM  768
#define CA   192

// Scratch (device globals)
__device__ __half g_w1t[CA * DIM];     // w1 fp16, n-major: [192][768]
__device__ __half g_w2t[DIM * CA];     // w2 fp16, n-major: [768][192]
__device__ __half g_act[LP * BT * CA]; // gelu(mix(h)) fp16: [25216][192]

// ---------------- PTX helpers ----------------
__device__ __forceinline__ void cp16(uint32_t s, const void* g) {
    asm volatile("cp.async.cg.shared.global [%0], [%1], 16;\n" :: "r"(s), "l"(g));
}
__device__ __forceinline__ void cp_commit() { asm volatile("cp.async.commit_group;\n"); }
__device__ __forceinline__ void cp_wait0()  { asm volatile("cp.async.wait_group 0;\n" ::: "memory"); }

__device__ __forceinline__ void ldsm_x4(uint32_t a[4], uint32_t saddr) {
    asm volatile("ldmatrix.sync.aligned.m8n8.x4.shared.b16 {%0,%1,%2,%3}, [%4];\n"
                 : "=r"(a[0]), "=r"(a[1]), "=r"(a[2]), "=r"(a[3]) : "r"(saddr));
}
__device__ __forceinline__ void mma_f16(float c[4], const uint32_t a[4], const uint32_t b[2]) {
    asm volatile(
        "mma.sync.aligned.m16n8k16.row.col.f32.f16.f16.f32 "
        "{%0,%1,%2,%3}, {%4,%5,%6,%7}, {%8,%9}, {%0,%1,%2,%3};\n"
        : "+f"(c[0]), "+f"(c[1]), "+f"(c[2]), "+f"(c[3])
        : "r"(a[0]), "r"(a[1]), "r"(a[2]), "r"(a[3]), "r"(b[0]), "r"(b[1]));
}
__device__ __forceinline__ float gelu_exact(float v) {
    return 0.5f * v * (1.0f + erff(v * 0.70710678118654752f));
}
__device__ __forceinline__ float red8(float v) {   // sum over gid (lanes ^4,^8,^16)
    v += __shfl_xor_sync(0xffffffffu, v, 4);
    v += __shfl_xor_sync(0xffffffffu, v, 8);
    v += __shfl_xor_sync(0xffffffffu, v, 16);
    return v;
}
__device__ __forceinline__ uint32_t pack_h2(float a, float b) {
    __half2 h = __floats2half2_rn(a, b);
    return *(uint32_t*)&h;
}

// ----- prep: transpose + fp32->fp16: w1t[n][k]=w1[k][n]; w2t[n][k]=w2[k][n] -----
__global__ void prep_kernel(const float* __restrict__ w1,
                            const float* __restrict__ w2,
                            __half* __restrict__ w1t,
                            __half* __restrict__ w2t) {
    __shared__ float t[32][33];
    int b = blockIdx.x;
    const float* in; __half* outp; int R, C, bx, by;
    if (b < 144) { in = w1; outp = w1t; R = DIM; C = CA;  bx = (b % 6) * 32;  by = (b / 6) * 32; }
    else { b -= 144; in = w2; outp = w2t; R = CA;  C = DIM; bx = (b % 24) * 32; by = (b / 24) * 32; }
    int tx = threadIdx.x, ty = threadIdx.y;
    #pragma unroll
    for (int i = 0; i < 32; i += 8)
        t[ty + i][tx] = in[(size_t)(by + ty + i) * C + bx + tx];
    __syncthreads();
    #pragma unroll
    for (int i = 0; i < 32; i += 8)
        outp[(size_t)(bx + ty + i) * R + by + tx] = __float2half(t[tx][ty + i]);
}

// ================= G1: g = gelu(mix(x @ w1 + b1)), fp16 MMA =================
// CTA: 64 rows x 192 cols, K=768 in 12 chunks of 64.
#define G1_PITCH 144                    // bytes per row (72 fp16; 9 granules, odd)
#define G1_ABYT  (64 * G1_PITCH)        // 9216
#define G1_BUF   (G1_ABYT + CA * G1_PITCH)   // 36864 per buffer
#define G1_SMEM  (2 * G1_BUF)           // 73728 -> 2 CTAs/SM

__global__ void __launch_bounds__(256, 2)
g1_kernel(const float* __restrict__ x,
          const float* __restrict__ b1,
          const float* __restrict__ cw,
          const float* __restrict__ cb)
{
    extern __shared__ char smem[];
    const uint32_t smem_u = (uint32_t)__cvta_generic_to_shared(smem);

    const int tid  = threadIdx.x;
    const int wid  = tid >> 5;
    const int lane = tid & 31;
    const int gid  = lane >> 2;
    const int ctig = lane & 3;

    const int l    = blockIdx.x >> 1;
    const int half = blockIdx.x & 1;
    const int lsrc = (l == 0) ? 1 : l;
    const float* xA = x + ((size_t)lsrc * BT + half * 64) * DIM;

    const int wm = wid & 1;            // rows wm*32..+31
    const int wn = wid >> 1;           // cols wn*48..+47

    // ldmatrix per-lane byte offsets
    const int a_lane = (lane & 15) * G1_PITCH + ((lane >> 4) << 4);
    const int b_lane = ((lane & 7) + ((lane >> 4) << 3)) * G1_PITCH + (((lane >> 3) & 1) << 4);

    // A staging coords: 512 segs (64 rows x 8 segs of 8 fp32 -> 16B fp16)
    const int ar0 = tid >> 3,        as0 = tid & 3 ? (tid & 7) : (tid & 7); // row/seg for idx=tid
    const int ar1 = (tid + 256) >> 3, as1 = (tid + 256) & 7;
    const int aseg0 = tid & 7;

    float acc[2][6][4];
    #pragma unroll
    for (int i = 0; i < 2; i++)
        #pragma unroll
        for (int j = 0; j < 6; j++)
            #pragma unroll
            for (int k = 0; k < 4; k++) acc[i][j][k] = 0.0f;

    float4 xv[4];   // A prefetch: 2 segs x 2 float4

    auto ldgA = [&](int kc) {
        xv[0] = *(const float4*)(xA + (size_t)ar0 * DIM + kc + aseg0 * 8);
        xv[1] = *(const float4*)(xA + (size_t)ar0 * DIM + kc + aseg0 * 8 + 4);
        xv[2] = *(const float4*)(xA + (size_t)ar1 * DIM + kc + as1 * 8);
        xv[3] = *(const float4*)(xA + (size_t)ar1 * DIM + kc + as1 * 8 + 4);
    };
    auto stsA = [&](int buf) {
        uint32_t base = smem_u + buf * G1_BUF;
        uint4 u0, u1;
        u0.x = pack_h2(xv[0].x, xv[0].y); u0.y = pack_h2(xv[0].z, xv[0].w);
        u0.z = pack_h2(xv[1].x, xv[1].y); u0.w = pack_h2(xv[1].z, xv[1].w);
        u1.x = pack_h2(xv[2].x, xv[2].y); u1.y = pack_h2(xv[2].z, xv[2].w);
        u1.z = pack_h2(xv[3].x, xv[3].y); u1.w = pack_h2(xv[3].z, xv[3].w);
        asm volatile("st.shared.v4.b32 [%0], {%1,%2,%3,%4};" ::
            "r"(base + ar0 * G1_PITCH + aseg0 * 16), "r"(u0.x), "r"(u0.y), "r"(u0.z), "r"(u0.w));
        asm volatile("st.shared.v4.b32 [%0], {%1,%2,%3,%4};" ::
            "r"(base + ar1 * G1_PITCH + as1 * 16), "r"(u1.x), "r"(u1.y), "r"(u1.z), "r"(u1.w));
    };
    auto cpB = [&](int buf, int kc) {
        uint32_t base = smem_u + buf * G1_BUF + G1_ABYT;
        #pragma unroll
        for (int i = 0; i < 6; i++) {           // 192 rows x 8 segs of 8 fp16
            int idx = tid + (i << 8);
            int row = idx >> 3, seg = idx & 7;
            cp16(base + row * G1_PITCH + seg * 16,
                 g_w1t + (size_t)row * DIM + kc + seg * 8);
        }
        cp_commit();
    };

    // prologue
    ldgA(0);
    cpB(0, 0);

    #pragma unroll 1
    for (int ic = 0; ic < 12; ic++) {
        const int buf = ic & 1;
        cp_wait0();                 // B_ic landed
        stsA(buf);                  // A_ic from regs
        __syncthreads();

        if (ic + 1 < 12) {          // prefetch next chunk (overlaps MMA)
            ldgA((ic + 1) * 64);
            cpB(buf ^ 1, (ic + 1) * 64);
        }

        const uint32_t Au = smem_u + buf * G1_BUF;
        const uint32_t Bu = Au + G1_ABYT;
        #pragma unroll
        for (int ks = 0; ks < 4; ks++) {        // 4 k16 steps
            uint32_t a0[4], a1[4];
            ldsm_x4(a0, Au + (wm * 32 +  0) * G1_PITCH + ks * 32 + a_lane);
            ldsm_x4(a1, Au + (wm * 32 + 16) * G1_PITCH + ks * 32 + a_lane);
            #pragma unroll
            for (int p = 0; p < 3; p++) {
                uint32_t bf[4];
                ldsm_x4(bf, Bu + (wn * 48 + p * 16) * G1_PITCH + ks * 32 + b_lane);
                mma_f16(acc[0][2 * p],     a0, bf);
                mma_f16(acc[1][2 * p],     a1, bf);
                mma_f16(acc[0][2 * p + 1], a0, bf + 2);
                mma_f16(acc[1][2 * p + 1], a1, bf + 2);
            }
        }
        __syncthreads();
    }

    // ---- epilogue: +b1, temporal mixing (shfl over gid = frame t), GELU, store ----
    const float tA0 = (gid < 7) ? (float)(gid + 1) : 0.0f;
    const float tA1 = (float)gid;
    const float tA2 = (gid >= 1) ? (float)(gid - 1) : 0.0f;
    const float tT7 = (float)(7 - gid);
    const int mbase = l * BT + half * 64;

    #pragma unroll
    for (int nt = 0; nt < 6; nt++) {
        int c = wn * 48 + nt * 8 + 2 * ctig;
        float b1a = b1[c],     b1b = b1[c + 1];
        float cba = cb[c],     cbb = cb[c + 1];
        float aA  = tA0 * cw[3 * c]     + tA1 * cw[3 * c + 1] + tA2 * cw[3 * c + 2] - tT7;
        float aB  = tA0 * cw[3 * c + 3] + tA1 * cw[3 * c + 4] + tA2 * cw[3 * c + 5] - tT7;
        #pragma unroll
        for (int mt = 0; mt < 2; mt++) {
            int r0 = wm * 32 + mt * 16 + gid;
            float v0 = acc[mt][nt][0] + b1a;
            float v1 = acc[mt][nt][1] + b1b;
            float v2 = acc[mt][nt][2] + b1a;   // row r0+8
            float v3 = acc[mt][nt][3] + b1b;
            if (l > 0) {
                float s0 = red8(aA * v0);
                float s1 = red8(aB * v1);
                float s2 = red8(aA * v2);
                float s3 = red8(aB * v3);
                v0 += s0 * (1.0f / 28.0f) + cba;
                v1 += s1 * (1.0f / 28.0f) + cbb;
                v2 += s2 * (1.0f / 28.0f) + cba;
                v3 += s3 * (1.0f / 28.0f) + cbb;
            }
            __half2* gp0 = (__half2*)(g_act + (size_t)(mbase + r0) * CA + c);
            __half2* gp1 = (__half2*)(g_act + (size_t)(mbase + r0 + 8) * CA + c);
            *gp0 = __floats2half2_rn(gelu_exact(v0), gelu_exact(v1));
            *gp1 = __floats2half2_rn(gelu_exact(v2), gelu_exact(v3));
        }
    }
}

// ================= G2: out = g @ w2 + b2 + x, fp16 MMA, single K stage ==========
#define G2_PITCH 400                    // bytes per row (200 fp16; 25 granules, odd)
#define G2_ABYT  (128 * G2_PITCH)       // 51200
#define G2_SMEM  (2 * G2_ABYT)          // 102400 -> 2 CTAs/SM

__global__ void __launch_bounds__(256, 2)
g2_kernel(const float* __restrict__ x,
          const float* __restrict__ b2,
          float* __restrict__ out)
{
    extern __shared__ char smem[];
    const uint32_t As_u = (uint32_t)__cvta_generic_to_shared(smem);
    const uint32_t Bs_u = As_u + G2_ABYT;

    const int tid  = threadIdx.x;
    const int wid  = tid >> 5;
    const int lane = tid & 31;
    const int gid  = lane >> 2;
    const int ctig = lane & 3;

    const int mtile = blockIdx.x;      // 0..196
    const int ntile = blockIdx.y;      // 0..5

    const int wm = wid & 1;            // rows wm*64..+63
    const int wn = wid >> 1;           // cols wn*32..+31

    const int a_lane = (lane & 15) * G2_PITCH + ((lane >> 4) << 4);
    const int b_lane = ((lane & 7) + ((lane >> 4) << 3)) * G2_PITCH + (((lane >> 3) & 1) << 4);

    // stage A (128x192 fp16) and B (128x192 fp16): 24 segs of 16B per row
    const __half* Ag = g_act + (size_t)(mtile * BT) * CA;
    const __half* Bg = g_w2t + (size_t)(ntile * 128) * CA;
    #pragma unroll
    for (int i = 0; i < 12; i++) {
        int idx = tid + (i << 8);          // 3072 tasks: seg = idx>>7, row = idx&127
        int row = idx & 127, seg = idx >> 7;
        cp16(As_u + row * G2_PITCH + seg * 16, Ag + (size_t)row * CA + seg * 8);
        cp16(Bs_u + row * G2_PITCH + seg * 16, Bg + (size_t)row * CA + seg * 8);
    }
    cp_commit();

    float acc[4][4][4];
    #pragma unroll
    for (int i = 0; i < 4; i++)
        #pragma unroll
        for (int j = 0; j < 4; j++)
            #pragma unroll
            for (int k = 0; k < 4; k++) acc[i][j][k] = 0.0f;

    cp_wait0();
    __syncthreads();

    #pragma unroll
    for (int ks = 0; ks < 12; ks++) {      // 12 k16 steps, zero barriers
        uint32_t a[4][4];
        #pragma unroll
        for (int mt = 0; mt < 4; mt++)
            ldsm_x4(a[mt], As_u + (wm * 64 + mt * 16) * G2_PITCH + ks * 32 + a_lane);
        #pragma unroll
        for (int p = 0; p < 2; p++) {
            uint32_t bf[4];
            ldsm_x4(bf, Bs_u + (wn * 32 + p * 16) * G2_PITCH + ks * 32 + b_lane);
            #pragma unroll
            for (int mt = 0; mt < 4; mt++) {
                mma_f16(acc[mt][2 * p],     a[mt], bf);
                mma_f16(acc[mt][2 * p + 1], a[mt], bf + 2);
            }
        }
    }

    // ---- epilogue: +b2 +x residual (fp32) ----
    const size_t mg0 = (size_t)mtile * BT;
    #pragma unroll
    for (int nt = 0; nt < 4; nt++) {
        int cg = ntile * 128 + wn * 32 + nt * 8 + 2 * ctig;
        float2 bb = *(const float2*)(b2 + cg);
        #pragma unroll
        for (int mt = 0; mt < 4; mt++) {
            int r = wm * 64 + mt * 16 + gid;
            size_t o0 = (mg0 + r) * DIM + cg;
            size_t o1 = o0 + (size_t)8 * DIM;
            float2 x0 = *(const float2*)(x + o0);
            float2 x1 = *(const float2*)(x + o1);
            float2 v0, v1;
            v0.x = acc[mt][nt][0] + bb.x + x0.x;
            v0.y = acc[mt][nt][1] + bb.y + x0.y;
            v1.x = acc[mt][nt][2] + bb.x + x1.x;
            v1.y = acc[mt][nt][3] + bb.y + x1.y;
            *(float2*)(out + o0) = v0;
            *(float2*)(out + o1) = v1;
        }
    }
}

extern "C" void kernel_launch(void* const* d_in, const int* in_sizes, int n_in,
                              void* d_out, int out_size) {
    const float* x  = (const float*)d_in[0];
    const float* w1 = (const float*)d_in[1];
    const float* b1 = (const float*)d_in[2];
    const float* cw = (const float*)d_in[3];
    const float* cb = (const float*)d_in[4];
    const float* w2 = (const float*)d_in[5];
    const float* b2 = (const float*)d_in[6];
    float* out = (float*)d_out;

    __half *w1t, *w2t;
    cudaGetSymbolAddress((void**)&w1t, g_w1t);
    cudaGetSymbolAddress((void**)&w2t, g_w2t);

    prep_kernel<<<288, dim3(32, 8)>>>(w1, w2, w1t, w2t);

    cudaFuncSetAttribute(g1_kernel, cudaFuncAttributeMaxDynamicSharedMemorySize, G1_SMEM);
    g1_kernel<<<LP * 2, 256, G1_SMEM>>>(x, b1, cw, cb);

    cudaFuncSetAttribute(g2_kernel, cudaFuncAttributeMaxDynamicSharedMemorySize, G2_SMEM);
    g2_kernel<<<dim3(LP, 6), 256, G2_SMEM>>>(x, b2, out);
}